// round 16
// baseline (speedup 1.0000x reference)
#include <cuda_runtime.h>
#include <cuda_fp16.h>
#include <math.h>
#include <stdint.h>

#define D        256
#define MAXN     32768
#define MAXM     8192
#define MAXMP    6656
#define TILE     128
#define INFBITS  0x7F800000u
#define MARGIN_F 0.075f
#define TIECAP   4096
#define CAP      192
#define E2A      0.25f
#define CB       0.55f
#define CBLO     0.35f
#define PADQ     30000.0f

// ---------------- scratch (__device__ globals: no allocations allowed) ----------------
__device__ unsigned g_keys[MAXN];
__device__ unsigned g_hist1[65536];
__device__ unsigned g_hist2[65536];
__device__ unsigned g_kthhi;
__device__ unsigned g_need1;
__device__ unsigned g_kth;
__device__ int      g_needTies;
__device__ int      g_counter;
__device__ int      g_tiecnt;
__device__ int      g_tielist[TIECAP];
__device__ int      g_is64;
__device__ int      g_selidx[MAXM];
__device__ float    g_emb[MAXM * D];
__device__ __half   g_embh[MAXM * D];
__device__ int      g_lab[MAXM];
__device__ float    g_sqn[MAXM];
__device__ float    g_hp[MAXM];
__device__ int      g_poscnt[MAXM];
__device__ unsigned g_t1[MAXM];
__device__ unsigned g_t2[MAXM];
__device__ int      g_candcnt[MAXM];
__device__ int      g_cand[MAXM * CAP];
__device__ float    g_loss[MAXM];
__device__ int      g_validf[MAXM];
__device__ __half   g_dsqh[(size_t)MAXMP * MAXMP];   // approx d^2, upper tiles only, fp16

// ---------------- helpers ----------------
__device__ __forceinline__ uint32_t smem_u32(const void* p) {
    uint32_t a;
    asm("{ .reg .u64 t; cvta.to.shared.u64 t, %1; cvt.u32.u64 %0, t; }" : "=r"(a) : "l"(p));
    return a;
}
#define SW128(off) ((off) ^ (((off) >> 3) & 0x70))

__device__ __forceinline__ void ldsm_x4(uint32_t& r0, uint32_t& r1, uint32_t& r2, uint32_t& r3,
                                        uint32_t addr) {
    asm volatile("ldmatrix.sync.aligned.m8n8.x4.shared.b16 {%0,%1,%2,%3}, [%4];"
                 : "=r"(r0), "=r"(r1), "=r"(r2), "=r"(r3) : "r"(addr));
}
__device__ __forceinline__ void mma16816(float& c0, float& c1, float& c2, float& c3,
                                         uint32_t a0, uint32_t a1, uint32_t a2, uint32_t a3,
                                         uint32_t b0, uint32_t b1) {
    asm volatile(
        "mma.sync.aligned.m16n8k16.row.col.f32.f16.f16.f32 "
        "{%0,%1,%2,%3}, {%4,%5,%6,%7}, {%8,%9}, {%0,%1,%2,%3};"
        : "+f"(c0), "+f"(c1), "+f"(c2), "+f"(c3)
        : "r"(a0), "r"(a1), "r"(a2), "r"(a3), "r"(b0), "r"(b1));
}

// pairwiseA smem layout (dynamic):
// [0, 16384)      SA fp16 tile (mainloop)   } staging half[128][136] reuses [0, 34816)
// [16384, 32768)  SB fp16 tile (mainloop)   }
#define PW_STAGE  0
#define PW_SA     0
#define PW_SB     16384
#define PW_SQI    34816
#define PW_SQJ    (PW_SQI + 512)
#define PW_HP2I   (PW_SQJ + 512)
#define PW_HP2J   (PW_HP2I + 512)
#define PW_LABI   (PW_HP2J + 512)
#define PW_LABJ   (PW_LABI + 256)
#define PW_RT1    (PW_LABJ + 256)
#define PW_RT2    (PW_RT1 + 512)
#define PW_CT1    (PW_RT2 + 512)
#define PW_CT2    (PW_CT1 + 512)
#define PW_SMEM   (PW_CT2 + 512)

// ---------------- setup ----------------
__global__ void setup_kernel(const float* __restrict__ conf, int N) {
    int stride = gridDim.x * blockDim.x;
    int t0 = blockIdx.x * blockDim.x + threadIdx.x;
    for (int i = t0; i < 65536; i += stride) { g_hist1[i] = 0u; g_hist2[i] = 0u; }
    for (int i = t0; i < MAXM; i += stride) { g_t1[i] = INFBITS; g_t2[i] = INFBITS; g_candcnt[i] = 0; }
    for (int i = t0; i < N; i += stride) {
        unsigned u = __float_as_uint(conf[i]);
        u = (u & 0x80000000u) ? ~u : (u | 0x80000000u);
        g_keys[i] = u;
    }
    if (t0 == 0) { g_counter = 0; g_tiecnt = 0; }
}

// ---------------- top-k select (two-level 16-bit histogram) ----------------
__global__ void hist1_kernel(int N) {
    for (int i = blockIdx.x * blockDim.x + threadIdx.x; i < N; i += gridDim.x * blockDim.x)
        atomicAdd(&g_hist1[g_keys[i] >> 16], 1u);
}

__device__ void scan_pick(const unsigned* __restrict__ hist, unsigned target,
                          unsigned* outBin, unsigned* outNeed) {
    __shared__ unsigned csum[1024];
    int c = threadIdx.x;
    unsigned mysum = 0;
    int b0 = c * 64;
#pragma unroll 8
    for (int b = 0; b < 64; b++) mysum += hist[b0 + b];
    csum[c] = mysum;
    __syncthreads();
    for (int off = 1; off < 1024; off <<= 1) {
        unsigned add = (c + off < 1024) ? csum[c + off] : 0u;
        __syncthreads();
        csum[c] += add;
        __syncthreads();
    }
    unsigned suf = csum[c] - mysum;
    if (suf < target && target <= suf + mysum) {
        unsigned rem = target - suf, cum = 0;
        for (int b = 63; b >= 0; b--) {
            unsigned h = hist[b0 + b];
            if (cum + h >= rem) { *outBin = (unsigned)(b0 + b); *outNeed = rem - cum; break; }
            cum += h;
        }
    }
}

__global__ void scan1_kernel(const int* __restrict__ tagsw, int N, int K) {
    __shared__ int sbad;
    if (threadIdx.x == 0) sbad = 0;
    __syncthreads();
    int bad = 0;
    for (int i = threadIdx.x * 2 + 1; i < N; i += 2 * blockDim.x)
        if (tagsw[i] != 0) bad = 1;
    if (bad) atomicOr(&sbad, 1);
    __syncthreads();
    if (threadIdx.x == 0) g_is64 = sbad ? 0 : 1;
    scan_pick(g_hist1, (unsigned)K, &g_kthhi, &g_need1);
}

__global__ void hist2_kernel(int N) {
    unsigned hi = g_kthhi;
    for (int i = blockIdx.x * blockDim.x + threadIdx.x; i < N; i += gridDim.x * blockDim.x) {
        unsigned k = g_keys[i];
        if ((k >> 16) == hi) atomicAdd(&g_hist2[k & 0xFFFFu], 1u);
    }
}

__global__ void scan2_kernel() {
    __shared__ unsigned bin, need;
    scan_pick(g_hist2, g_need1, &bin, &need);
    __syncthreads();
    if (threadIdx.x == 0) { g_kth = (g_kthhi << 16) | bin; g_needTies = (int)need; }
}

__global__ void compact_kernel(int N) {
    unsigned kth = g_kth;
    for (int i = blockIdx.x * blockDim.x + threadIdx.x; i < N; i += gridDim.x * blockDim.x) {
        unsigned k = g_keys[i];
        if (k > kth) {
            int p = atomicAdd(&g_counter, 1);
            g_selidx[p] = i;
        } else if (k == kth) {
            int p = atomicAdd(&g_tiecnt, 1);
            if (p < TIECAP) g_tielist[p] = i;
        }
    }
}

__global__ void ties_kernel(int N) {
    if (threadIdx.x != 0) return;
    int need = g_needTies;
    int base = g_counter;
    int tc = g_tiecnt;
    if (tc <= TIECAP) {
        int last = -1;
        for (int r = 0; r < need; r++) {
            int best = 0x7FFFFFFF;
            for (int t = 0; t < tc; t++) {
                int v = g_tielist[t];
                if (v > last && v < best) best = v;
            }
            g_selidx[base + r] = best;
            last = best;
        }
    } else {
        unsigned kth = g_kth;
        int taken = 0;
        for (int i = 0; i < N && taken < need; i++)
            if (g_keys[i] == kth) g_selidx[base + taken++] = i;
    }
}

// ---------------- gather + fp16 hi + norms / labels ----------------
__global__ void gather_kernel(const float* __restrict__ emb, const int* __restrict__ tagsw, int K) {
    __shared__ float red[256];
    int m = blockIdx.x;
    int t = threadIdx.x;
    int idx = (m < K) ? g_selidx[m] : 0;
    float v = (m < K) ? emb[(size_t)idx * D + t] : 0.f;
    g_emb[m * D + t] = v;
    g_embh[m * D + t] = __float2half_rn(v);
    red[t] = v * v;
    __syncthreads();
    for (int s = 128; s > 0; s >>= 1) {
        if (t < s) red[t] += red[t + s];
        __syncthreads();
    }
    if (t == 0) {
        g_sqn[m] = (m < K) ? red[0] : 0.f;
        int lab = -1;
        if (m < K) lab = g_is64 ? tagsw[2 * idx] : tagsw[idx];
        g_lab[m] = lab;
    }
}

// ---------------- hard positives (fp32 exact, sparse) ----------------
__global__ void hardpos_kernel(int K, int MPAD) {
    __shared__ int slab[MAXM];
    for (int i = threadIdx.x; i < K; i += blockDim.x) slab[i] = g_lab[i];
    __syncthreads();
    int w = threadIdx.x >> 5, lane = threadIdx.x & 31;
    int a = blockIdx.x * 8 + w;
    if (a >= MPAD) return;
    if (a >= K) {
        if (lane == 0) { g_hp[a] = __uint_as_float(0xFF800000u); g_poscnt[a] = 0; }
        return;
    }
    int la = slab[a];
    float na = g_sqn[a];
    const float4* ea = (const float4*)(g_emb + a * D);
    float mx = __uint_as_float(0xFF800000u);
    int cnt = 0;
    for (int j = lane; j < K; j += 32) {
        if (j != a && slab[j] == la) {
            const float4* ej = (const float4*)(g_emb + j * D);
            float dot = 0.f;
#pragma unroll 8
            for (int q = 0; q < D / 4; q++) {
                float4 x = ea[q], y = ej[q];
                dot += x.x * y.x; dot += x.y * y.y; dot += x.z * y.z; dot += x.w * y.w;
            }
            float sq = na + g_sqn[j] - 2.f * dot;
            float d = sqrtf(fmaxf(sq, 0.f));
            mx = fmaxf(mx, d);
            cnt++;
        }
    }
    for (int o = 16; o; o >>= 1) {
        mx = fmaxf(mx, __shfl_xor_sync(0xffffffffu, mx, o));
        cnt += __shfl_xor_sync(0xffffffffu, cnt, o);
    }
    if (lane == 0) {
        g_hp[a] = cnt ? mx : __uint_as_float(0xFF800000u);
        g_poscnt[a] = cnt;
    }
}

// ---------------- pairwiseA: hi-only MMA -> d^2 thresholds + fp16 tile store ----------
__global__ __launch_bounds__(256)
void pairwiseA_kernel(int KSEL, int MPAD, int NT) {
    extern __shared__ char smem[];
    uint32_t sb = smem_u32(smem);
    float*    sqnI  = (float*)(smem + PW_SQI);
    float*    sqnJ  = (float*)(smem + PW_SQJ);
    float*    hp2I  = (float*)(smem + PW_HP2I);
    float*    hp2J  = (float*)(smem + PW_HP2J);
    unsigned short* labI = (unsigned short*)(smem + PW_LABI);
    unsigned short* labJ = (unsigned short*)(smem + PW_LABJ);
    unsigned* sRT1 = (unsigned*)(smem + PW_RT1);
    unsigned* sRT2 = (unsigned*)(smem + PW_RT2);
    unsigned* sCT1 = (unsigned*)(smem + PW_CT1);
    unsigned* sCT2 = (unsigned*)(smem + PW_CT2);
    __half* stage = (__half*)(smem + PW_STAGE);   // [128][136], used after mainloop

    int tid = threadIdx.x, wid = tid >> 5, lane = tid & 31;

    int t = blockIdx.x;
    float nf = (float)NT;
    int bi = (int)(nf + 0.5f - sqrtf((nf + 0.5f) * (nf + 0.5f) - 2.0f * (float)t));
    while (bi > 0 && bi * NT - (bi * (bi - 1)) / 2 > t) bi--;
    while ((bi + 1) * NT - ((bi + 1) * bi) / 2 <= t) bi++;
    int bj = bi + (t - (bi * NT - (bi * (bi - 1)) / 2));
    int gibase = bi * TILE, gjbase = bj * TILE;

    if (tid < 128) {
        int gi = gibase + tid, gj = gjbase + tid;
        sqnI[tid] = g_sqn[gi];
        sqnJ[tid] = g_sqn[gj];
        float hi = g_hp[gi], hj = g_hp[gj];
        hp2I[tid] = hi * hi;
        hp2J[tid] = hj * hj;
        labI[tid] = (unsigned short)g_lab[gi];
        labJ[tid] = (unsigned short)g_lab[gj];
        sRT1[tid] = INFBITS; sRT2[tid] = INFBITS;
        sCT1[tid] = INFBITS; sCT2[tid] = INFBITS;
    }

    int mi = wid & 1;
    int nj = wid >> 1;
    int R = mi * 64, C = nj * 32;

    float acc[4][4][4];
#pragma unroll
    for (int a = 0; a < 4; a++)
#pragma unroll
        for (int b = 0; b < 4; b++)
#pragma unroll
            for (int c = 0; c < 4; c++) acc[a][b][c] = 0.f;

    for (int ch = 0; ch < 4; ch++) {
        for (int u = tid; u < 2048; u += 256) {
            int tile = u >> 10;
            int v = u & 1023;
            int row = v >> 3;
            int seg = v & 7;
            int base = tile ? gjbase : gibase;
            uint4 val = *(const uint4*)(g_embh + (size_t)(base + row) * D + ch * 64 + seg * 8);
            *(uint4*)(smem + (tile ? PW_SB : PW_SA) + SW128((uint32_t)(row * 128 + seg * 16))) = val;
        }
        __syncthreads();

        int lrow = lane & 15;
        int lk16 = (lane >> 4) * 16;
#pragma unroll
        for (int ks = 0; ks < 4; ks++) {
            int ko = ks * 32 + lk16;
            uint32_t ah[4][4], bh[2][4];
#pragma unroll
            for (int mf = 0; mf < 4; mf++) {
                uint32_t addr = sb + PW_SA + SW128((uint32_t)((R + mf * 16 + lrow) * 128 + ko));
                ldsm_x4(ah[mf][0], ah[mf][1], ah[mf][2], ah[mf][3], addr);
            }
#pragma unroll
            for (int h = 0; h < 2; h++) {
                uint32_t addr = sb + PW_SB + SW128((uint32_t)((C + h * 16 + lrow) * 128 + ko));
                ldsm_x4(bh[h][0], bh[h][1], bh[h][2], bh[h][3], addr);
            }
#pragma unroll
            for (int mf = 0; mf < 4; mf++) {
#pragma unroll
                for (int nfr = 0; nfr < 4; nfr++) {
                    int h = nfr >> 1, s = nfr & 1;
                    float* cc = acc[mf][nfr];
                    mma16816(cc[0], cc[1], cc[2], cc[3],
                             ah[mf][0], ah[mf][1], ah[mf][2], ah[mf][3],
                             bh[h][s], bh[h][s + 2]);
                }
            }
        }
        __syncthreads();
    }

    // ---------------- epilogue: thresholds + staging ----------------
    const float INFv = __uint_as_float(INFBITS);
    int lr = lane >> 2, tig = lane & 3;

    // column meta + per-column running mins (registers)
    float cT1[4][2], cT2[4][2];
    float sjc[4][2], hp2c[4][2];
    unsigned short labc[4][2];
    bool cokv[4][2];
#pragma unroll
    for (int nfr = 0; nfr < 4; nfr++)
#pragma unroll
        for (int p = 0; p < 2; p++) {
            int col = C + nfr * 8 + 2 * tig + p;
            sjc[nfr][p]  = sqnJ[col];
            hp2c[nfr][p] = hp2J[col];
            labc[nfr][p] = labJ[col];
            cokv[nfr][p] = (gjbase + col) < KSEL;
            cT1[nfr][p] = INFv; cT2[nfr][p] = INFv;
        }

#pragma unroll
    for (int mf = 0; mf < 4; mf++) {
        int r0 = R + mf * 16 + lr, r1 = r0 + 8;
        bool ok0 = (gibase + r0) < KSEL, ok1 = (gibase + r1) < KSEL;
        unsigned short lab0 = labI[r0], lab1 = labI[r1];
        float sq0 = sqnI[r0], sq1 = sqnI[r1];
        float h20 = hp2I[r0], h21 = hp2I[r1];
        float rT1_0 = INFv, rT2_0 = INFv, rT1_1 = INFv, rT2_1 = INFv;
#pragma unroll
        for (int nfr = 0; nfr < 4; nfr++) {
#pragma unroll
            for (int p = 0; p < 2; p++) {
                int col = C + nfr * 8 + 2 * tig + p;
                bool ck = cokv[nfr][p];
                unsigned short lc = labc[nfr][p];
                float sjv = sjc[nfr][p], h2c = hp2c[nfr][p];

                float q0 = fmaxf(sq0 + sjv - 2.f * acc[mf][nfr][p], 0.f);
                float q1 = fmaxf(sq1 + sjv - 2.f * acc[mf][nfr][2 + p], 0.f);

                bool v0 = ok0 && ck && (lab0 != lc);
                bool v1 = ok1 && ck && (lab1 != lc);
                if (v0) {
                    rT1_0 = fminf(rT1_0, q0);
                    if (q0 > h20 + E2A) rT2_0 = fminf(rT2_0, q0);
                    cT1[nfr][p] = fminf(cT1[nfr][p], q0);
                    if (q0 > h2c + E2A) cT2[nfr][p] = fminf(cT2[nfr][p], q0);
                }
                if (v1) {
                    rT1_1 = fminf(rT1_1, q1);
                    if (q1 > h21 + E2A) rT2_1 = fminf(rT2_1, q1);
                    cT1[nfr][p] = fminf(cT1[nfr][p], q1);
                    if (q1 > h2c + E2A) cT2[nfr][p] = fminf(cT2[nfr][p], q1);
                }
                stage[r0 * 136 + col] = __float2half_rn((ok0 && ck) ? q0 : PADQ);
                stage[r1 * 136 + col] = __float2half_rn((ok1 && ck) ? q1 : PADQ);
            }
        }
#pragma unroll
        for (int o = 1; o <= 2; o <<= 1) {
            rT1_0 = fminf(rT1_0, __shfl_xor_sync(0xffffffffu, rT1_0, o));
            rT2_0 = fminf(rT2_0, __shfl_xor_sync(0xffffffffu, rT2_0, o));
            rT1_1 = fminf(rT1_1, __shfl_xor_sync(0xffffffffu, rT1_1, o));
            rT2_1 = fminf(rT2_1, __shfl_xor_sync(0xffffffffu, rT2_1, o));
        }
        if (tig == 0) {
            if (rT1_0 < INFv) atomicMin(&sRT1[r0], __float_as_uint(rT1_0));
            if (rT2_0 < INFv) atomicMin(&sRT2[r0], __float_as_uint(rT2_0));
            if (rT1_1 < INFv) atomicMin(&sRT1[r1], __float_as_uint(rT1_1));
            if (rT2_1 < INFv) atomicMin(&sRT2[r1], __float_as_uint(rT2_1));
        }
    }
#pragma unroll
    for (int nfr = 0; nfr < 4; nfr++)
#pragma unroll
        for (int p = 0; p < 2; p++) {
#pragma unroll
            for (int o = 4; o <= 16; o <<= 1) {
                cT1[nfr][p] = fminf(cT1[nfr][p], __shfl_xor_sync(0xffffffffu, cT1[nfr][p], o));
                cT2[nfr][p] = fminf(cT2[nfr][p], __shfl_xor_sync(0xffffffffu, cT2[nfr][p], o));
            }
        }
    if (lane < 4) {
#pragma unroll
        for (int nfr = 0; nfr < 4; nfr++)
#pragma unroll
            for (int p = 0; p < 2; p++) {
                int col = C + nfr * 8 + 2 * tig + p;
                if (cT1[nfr][p] < INFv) atomicMin(&sCT1[col], __float_as_uint(cT1[nfr][p]));
                if (cT2[nfr][p] < INFv) atomicMin(&sCT2[col], __float_as_uint(cT2[nfr][p]));
            }
    }
    __syncthreads();
    if (tid < 128) {
        int gi = gibase + tid, gj = gjbase + tid;
        if (gi < KSEL) {
            if (sRT1[tid] != INFBITS) atomicMin(&g_t1[gi], sRT1[tid]);
            if (sRT2[tid] != INFBITS) atomicMin(&g_t2[gi], sRT2[tid]);
        }
        if (gj < KSEL) {
            if (sCT1[tid] != INFBITS) atomicMin(&g_t1[gj], sCT1[tid]);
            if (sCT2[tid] != INFBITS) atomicMin(&g_t2[gj], sCT2[tid]);
        }
    }
    // coalesced tile store (row-major, upper tile only)
    for (int u = tid; u < 2048; u += 256) {
        int r = u >> 4, seg = u & 15;
        uint4 v = *(uint4*)((char*)stage + r * 272 + seg * 16);
        *(uint4*)(g_dsqh + (size_t)(gibase + r) * MPAD + gjbase + seg * 8) = v;
    }
}

// ---------------- candscan: read matrix once, emit candidate lists ----------------
__global__ __launch_bounds__(256)
void candscan_kernel(int KSEL, int MPAD, int NT) {
    __shared__ float t1I[128], t2I[128], hp2I[128];
    __shared__ float t1J[128], t2J[128], hp2J[128];
    __shared__ unsigned short labI[128], labJ[128];
    int tid = threadIdx.x;

    int t = blockIdx.x;
    float nf = (float)NT;
    int bi = (int)(nf + 0.5f - sqrtf((nf + 0.5f) * (nf + 0.5f) - 2.0f * (float)t));
    while (bi > 0 && bi * NT - (bi * (bi - 1)) / 2 > t) bi--;
    while ((bi + 1) * NT - ((bi + 1) * bi) / 2 <= t) bi++;
    int bj = bi + (t - (bi * NT - (bi * (bi - 1)) / 2));
    int gibase = bi * TILE, gjbase = bj * TILE;

    if (tid < 128) {
        int gi = gibase + tid, gj = gjbase + tid;
        t1I[tid] = __uint_as_float(g_t1[gi]);
        t2I[tid] = __uint_as_float(g_t2[gi]);
        float h = g_hp[gi]; hp2I[tid] = h * h;
        labI[tid] = (unsigned short)g_lab[gi];
        t1J[tid] = __uint_as_float(g_t1[gj]);
        t2J[tid] = __uint_as_float(g_t2[gj]);
        h = g_hp[gj]; hp2J[tid] = h * h;
        labJ[tid] = (unsigned short)g_lab[gj];
    }
    __syncthreads();

    bool diag = (bi == bj);
    for (int e = tid; e < 16384; e += 256) {
        int r = e >> 7, c = e & 127;
        float qq = __half2float(g_dsqh[(size_t)(gibase + r) * MPAD + gjbase + c]);
        if (qq > 20000.f) continue;
        if (labI[r] == labJ[c]) continue;
        if (qq <= t1I[r] + CB || (qq > hp2I[r] - CBLO && qq <= t2I[r] + CB)) {
            int a = gibase + r;
            int p = atomicAdd(&g_candcnt[a], 1);
            if (p < CAP) g_cand[a * CAP + p] = gjbase + c;
        }
        if (!diag) {
            if (qq <= t1J[c] + CB || (qq > hp2J[c] - CBLO && qq <= t2J[c] + CB)) {
                int a = gjbase + c;
                int p = atomicAdd(&g_candcnt[a], 1);
                if (p < CAP) g_cand[a * CAP + p] = gibase + r;
            }
        }
    }
}

// ---------------- refine: exact fp32 on candidates (warp per anchor) ----------------
__global__ __launch_bounds__(256)
void refine_kernel(int K) {
    int tid = threadIdx.x, w = tid >> 5, ln = tid & 31;
    int i = blockIdx.x * 8 + w;
    if (i >= K) return;
    int pc = g_poscnt[i];
    if (!(pc > 0 && (K - 1 - pc) > 0)) {
        if (ln == 0) { g_loss[i] = 0.f; g_validf[i] = 0; }
        return;
    }
    float hp = g_hp[i];
    float sqni = g_sqn[i];
    int labi = g_lab[i];
    float xr[8];
    const float* xrow = g_emb + (size_t)i * D;
#pragma unroll
    for (int k = 0; k < 8; k++) xr[k] = xrow[ln * 8 + k];
    float negb = 3e30f, shnb = 3e30f;
    int nc = g_candcnt[i];
    if (nc <= CAP) {
        for (int c = 0; c < nc; c++) {
            int j = g_cand[i * CAP + c];
            const float* y = g_emb + (size_t)j * D;
            float4 ya = *(const float4*)(y + ln * 8);
            float4 yb = *(const float4*)(y + ln * 8 + 4);
            float s = xr[0] * ya.x + xr[1] * ya.y + xr[2] * ya.z + xr[3] * ya.w
                    + xr[4] * yb.x + xr[5] * yb.y + xr[6] * yb.z + xr[7] * yb.w;
#pragma unroll
            for (int o = 16; o; o >>= 1) s += __shfl_xor_sync(0xffffffffu, s, o);
            float d2 = sqni + g_sqn[j] - 2.f * s;
            float d = sqrtf(fmaxf(d2, 0.f));
            negb = fminf(negb, d);
            if (d > hp) shnb = fminf(shnb, d);
        }
    } else {
        // overflow fallback: exact full-row scan (rare; correctness first)
        for (int j = ln; j < K; j += 32) {
            if (g_lab[j] == labi) continue;
            const float4* ej = (const float4*)(g_emb + (size_t)j * D);
            const float4* ea = (const float4*)xrow;
            float dot = 0.f;
#pragma unroll 8
            for (int q = 0; q < D / 4; q++) {
                float4 x = ea[q], yv = ej[q];
                dot += x.x * yv.x; dot += x.y * yv.y; dot += x.z * yv.z; dot += x.w * yv.w;
            }
            float d2 = sqni + g_sqn[j] - 2.f * dot;
            float d = sqrtf(fmaxf(d2, 0.f));
            negb = fminf(negb, d);
            if (d > hp) shnb = fminf(shnb, d);
        }
#pragma unroll
        for (int o = 16; o; o >>= 1) {
            negb = fminf(negb, __shfl_xor_sync(0xffffffffu, negb, o));
            shnb = fminf(shnb, __shfl_xor_sync(0xffffffffu, shnb, o));
        }
    }
    if (ln == 0) {
        float hn = (shnb < 3e29f) ? shnb : negb;
        float per = hp - hn + MARGIN_F;
        g_loss[i] = per > 0.f ? per : 0.f;
        g_validf[i] = 1;
    }
}

// ---------------- finalize ----------------
__global__ void finalize_kernel(int KSEL, float* __restrict__ out) {
    __shared__ float ssum[32];
    __shared__ int scnt[32];
    float sum = 0.f; int cnt = 0;
    for (int a = threadIdx.x; a < KSEL; a += blockDim.x) {
        sum += g_loss[a];
        cnt += g_validf[a];
    }
    for (int o = 16; o; o >>= 1) {
        sum += __shfl_xor_sync(0xffffffffu, sum, o);
        cnt += __shfl_xor_sync(0xffffffffu, cnt, o);
    }
    int w = threadIdx.x >> 5, lane = threadIdx.x & 31;
    if (lane == 0) { ssum[w] = sum; scnt[w] = cnt; }
    __syncthreads();
    if (threadIdx.x < 32) {
        int nw = blockDim.x >> 5;
        sum = (threadIdx.x < nw) ? ssum[threadIdx.x] : 0.f;
        cnt = (threadIdx.x < nw) ? scnt[threadIdx.x] : 0;
        for (int o = 16; o; o >>= 1) {
            sum += __shfl_xor_sync(0xffffffffu, sum, o);
            cnt += __shfl_xor_sync(0xffffffffu, cnt, o);
        }
        if (threadIdx.x == 0) out[0] = (cnt > 0) ? sum / (float)cnt : 0.f;
    }
}

// ---------------- launch ----------------
extern "C" void kernel_launch(void* const* d_in, const int* in_sizes, int n_in,
                              void* d_out, int out_size) {
    const float* emb   = (const float*)d_in[0];
    const int*   tagsw = (const int*)d_in[1];
    const float* conf  = (const float*)d_in[2];
    int N = in_sizes[2];
    int K = (int)(0.2 * (double)N);
    int NT = (K + TILE - 1) / TILE;
    int MPAD = NT * TILE;
    int NTILES = NT * (NT + 1) / 2;

    cudaFuncSetAttribute(pairwiseA_kernel, cudaFuncAttributeMaxDynamicSharedMemorySize, PW_SMEM);

    setup_kernel<<<128, 256>>>(conf, N);
    hist1_kernel<<<64, 256>>>(N);
    scan1_kernel<<<1, 1024>>>(tagsw, N, K);
    hist2_kernel<<<64, 256>>>(N);
    scan2_kernel<<<1, 1024>>>();
    compact_kernel<<<64, 256>>>(N);
    ties_kernel<<<1, 32>>>(N);
    gather_kernel<<<MPAD, 256>>>(emb, tagsw, K);
    hardpos_kernel<<<(MPAD + 7) / 8, 256>>>(K, MPAD);
    pairwiseA_kernel<<<NTILES, 256, PW_SMEM>>>(K, MPAD, NT);
    candscan_kernel<<<NTILES, 256>>>(K, MPAD, NT);
    refine_kernel<<<(K + 7) / 8, 256>>>(K);
    finalize_kernel<<<1, 1024>>>(K, (float*)d_out);
}